// round 4
// baseline (speedup 1.0000x reference)
#include <cuda_runtime.h>
#include <math.h>

#define BATCH 64
#define NPTS  512
#define DIM   512
#define NIDS  32                     // track ids are in [-1, 32)
#define CHUNKS 16                    // dist blocks per batch
#define DBLOCKS (BATCH * CHUNKS)     // 1024
#define DTHREADS 256
#define DWARPS (DTHREADS / 32)       // 8
#define APW (NPTS / CHUNKS / DWARPS) // 4 anchors per warp

__device__ __constant__ float c_margin = 0.3f;
__device__ __constant__ float c_eps    = 1e-6f;

// scratch (no allocations allowed)
__device__ float g_partial[DBLOCKS];
__device__ int   g_cnt[DBLOCKS];
__device__ unsigned int g_ticket;    // zero-initialized; reset by last block

// ---------------------------------------------------------------------------
// Single fused kernel:
//   - per-batch id tables rebuilt per block (cheap, ~1us amortized)
//   - 2 distinct negative rows per batch cached in smem (native float4 array
//     -> guaranteed 16B alignment; R3 failed on a misaligned (float4*)float[]
//     reinterpret of shared memory)
//   - distances + masked hinge -> per-block partial
//   - last block (atomic ticket) reduces all partials and writes the output
//
// Closed-form replacement for argmax-of-mask (ids in [-1, 32)):
//   pos(i) = first[m] != i ? first[m] : second[m]     (needs count[m] >= 2)
//   neg(i) = ids[j1] != m ? j1 : j2                   (needs nvalid > count[m])
// ---------------------------------------------------------------------------
__global__ void dist_kernel(const float* __restrict__ feats,
                            const int*   __restrict__ ids,
                            float*       __restrict__ out,
                            int out_size)
{
    const int bk    = blockIdx.x;
    const int b     = bk / CHUNKS;
    const int chunk = bk % CHUNKS;
    const int wid   = threadIdx.x >> 5;
    const int lane  = threadIdx.x & 31;
    const int t     = threadIdx.x;

    __shared__ float4 s_neg4[2][DIM / 4];    // two distinct negative rows (16B aligned)
    __shared__ int s_first[NIDS];
    __shared__ int s_second[NIDS];
    __shared__ int s_count[NIDS];
    __shared__ int s_j1;      // first valid index overall
    __shared__ int s_j2;      // first valid index with id != ids[j1]
    __shared__ int s_idj1;    // ids[j1]
    __shared__ int s_nvalid;
    __shared__ float s_tot;
    __shared__ int   s_cnt;
    __shared__ int   s_last;
    __shared__ float s_red[DTHREADS];        // final-reduce scratch
    __shared__ int   s_redc[DTHREADS];

    if (t < NIDS) {
        s_first[t]  = 0x7fffffff;
        s_second[t] = 0x7fffffff;
        s_count[t]  = 0;
    }
    if (t == 0) {
        s_j1 = 0x7fffffff;
        s_j2 = 0x7fffffff;
        s_nvalid = 0;
        s_tot = 0.0f;
        s_cnt = 0;
        s_last = 0;
    }
    __syncthreads();

    // Pass 1: first occurrence per id, per-id counts, first valid overall.
    const int i0  = t;
    const int i1  = t + DTHREADS;
    const int id0 = ids[b * NPTS + i0];
    const int id1 = ids[b * NPTS + i1];
    if (id0 >= 0) {
        atomicMin(&s_first[id0], i0);
        atomicAdd(&s_count[id0], 1);
        atomicMin(&s_j1, i0);
    }
    if (id1 >= 0) {
        atomicMin(&s_first[id1], i1);
        atomicAdd(&s_count[id1], 1);
        atomicMin(&s_j1, i1);
    }
    int nv = __syncthreads_count(id0 >= 0);
    nv    += __syncthreads_count(id1 >= 0);
    if (t == 0) {
        s_nvalid = nv;
        s_idj1 = (s_j1 < NPTS) ? ids[b * NPTS + s_j1] : -2;
    }
    __syncthreads();

    // Pass 2: second occurrence per id; first valid with id != ids[j1].
    const int idj1 = s_idj1;
    if (id0 >= 0) {
        if (i0 != s_first[id0]) atomicMin(&s_second[id0], i0);
        if (id0 != idj1)        atomicMin(&s_j2, i0);
    }
    if (id1 >= 0) {
        if (i1 != s_first[id1]) atomicMin(&s_second[id1], i1);
        if (id1 != idj1)        atomicMin(&s_j2, i1);
    }
    __syncthreads();

    const int nvalid = s_nvalid;
    const int j1 = s_j1;
    const int j2 = s_j2;

    // Stage both negative rows into smem (float4, coalesced).
    if (t < 128) {
        if (j1 < NPTS)
            s_neg4[0][t] = ((const float4*)(feats + ((size_t)b * NPTS + j1) * DIM))[t];
    } else {
        if (j2 < NPTS)
            s_neg4[1][t - 128] = ((const float4*)(feats + ((size_t)b * NPTS + j2) * DIM))[t - 128];
    }
    __syncthreads();

    float w_tot = 0.0f;
    int   w_cnt = 0;

    const int a_base = chunk * (NPTS / CHUNKS) + wid * APW;
    const float eps = c_eps;

    for (int a = 0; a < APW; ++a) {
        const int i = a_base + a;
        const int m = ids[b * NPTS + i];          // hot in L1/L2
        if (m < 0) continue;
        const int cm = s_count[m];
        if (cm < 2) continue;                      // no positive
        if (nvalid - cm < 1) continue;             // no negative

        const int f = s_first[m];
        const int p = (f != i) ? f : s_second[m];
        const int sel = (idj1 != m) ? 0 : 1;

        const float4* __restrict__ fi =
            (const float4*)(feats + ((size_t)b * NPTS + i) * DIM);
        const float4* __restrict__ fp =
            (const float4*)(feats + ((size_t)b * NPTS + p) * DIM);
        const float4* fn = s_neg4[sel];

        float sap = 0.0f, san = 0.0f;
        #pragma unroll
        for (int k = 0; k < DIM / 4 / 32; ++k) {
            const int idx = k * 32 + lane;
            const float4 a4 = fi[idx];
            const float4 p4 = fp[idx];
            const float4 n4 = fn[idx];
            float d;
            d = a4.x - p4.x + eps; sap = fmaf(d, d, sap);
            d = a4.y - p4.y + eps; sap = fmaf(d, d, sap);
            d = a4.z - p4.z + eps; sap = fmaf(d, d, sap);
            d = a4.w - p4.w + eps; sap = fmaf(d, d, sap);
            d = a4.x - n4.x + eps; san = fmaf(d, d, san);
            d = a4.y - n4.y + eps; san = fmaf(d, d, san);
            d = a4.z - n4.z + eps; san = fmaf(d, d, san);
            d = a4.w - n4.w + eps; san = fmaf(d, d, san);
        }
        #pragma unroll
        for (int o = 16; o > 0; o >>= 1) {
            sap += __shfl_xor_sync(0xFFFFFFFFu, sap, o);
            san += __shfl_xor_sync(0xFFFFFFFFu, san, o);
        }
        if (lane == 0) {
            const float per = sqrtf(sap) - sqrtf(san) + c_margin;
            if (per > 0.0f) w_tot += per;
            w_cnt++;
        }
    }

    if (lane == 0) {
        atomicAdd(&s_tot, w_tot);
        atomicAdd(&s_cnt, w_cnt);
    }
    __syncthreads();

    // Publish partial, grab ticket; the last block finishes the job.
    if (t == 0) {
        g_partial[bk] = s_tot;
        g_cnt[bk]     = s_cnt;
        __threadfence();
        const unsigned int old = atomicAdd(&g_ticket, 1u);
        s_last = (old == DBLOCKS - 1);
    }
    __syncthreads();

    if (s_last) {
        // Deterministic final reduction: fixed strided order.
        float tot = 0.0f;
        int   cnt = 0;
        #pragma unroll
        for (int r = 0; r < DBLOCKS / DTHREADS; ++r) {
            tot += g_partial[r * DTHREADS + t];
            cnt += g_cnt[r * DTHREADS + t];
        }
        s_red[t]  = tot;
        s_redc[t] = cnt;
        __syncthreads();
        #pragma unroll
        for (int s = DTHREADS / 2; s > 0; s >>= 1) {
            if (t < s) { s_red[t] += s_red[t + s]; s_redc[t] += s_redc[t + s]; }
            __syncthreads();
        }
        if (t == 0) {
            const int c = s_redc[0];
            const float loss = (c > 0) ? (s_red[0] / (float)c) : 0.0f;
            if (out_size > 0) out[0] = loss;   // tracking_loss
            if (out_size > 1) out[1] = loss;   // loss_triplet
            if (out_size > 2) out[2] = 0.0f;   // loss_id
            g_ticket = 0;                      // reset for next graph replay
            __threadfence();
        }
    }
}

extern "C" void kernel_launch(void* const* d_in, const int* in_sizes, int n_in,
                              void* d_out, int out_size)
{
    const float* feats = (const float*)d_in[0];
    const int*   ids   = (const int*)d_in[1];
    float*       out   = (float*)d_out;

    dist_kernel<<<DBLOCKS, DTHREADS>>>(feats, ids, out, out_size);
}

// round 5
// speedup vs baseline: 1.1235x; 1.1235x over previous
#include <cuda_runtime.h>
#include <math.h>

#define BATCH 64
#define NPTS  512
#define DIM   512
#define NIDS  32                     // track ids are in [-1, 32)
#define CHUNKS 16                    // dist blocks per batch
#define DBLOCKS (BATCH * CHUNKS)     // 1024
#define DTHREADS 256
#define DWARPS (DTHREADS / 32)       // 8
#define APW (NPTS / CHUNKS / DWARPS) // 4 anchors per warp

__device__ __constant__ float c_margin = 0.3f;
__device__ __constant__ float c_eps    = 1e-6f;

// scratch (no allocations allowed)
__device__ float g_partial[DBLOCKS];
__device__ int   g_cnt[DBLOCKS];
__device__ unsigned int g_ticket;    // zero-initialized; reset by last block

// ---------------------------------------------------------------------------
// Single fused kernel (R2 dist body — all-LDG inner loop, negatives stay hot
// in L1 — plus ticket-based last-block finish; R4 showed smem-caching the
// negative rows is a net loss: it broke load MLP for rows that were already
// L1-resident).
//
// Closed-form replacement for argmax-of-mask (ids in [-1, 32)):
//   pos(i) = first[m] != i ? first[m] : second[m]     (needs count[m] >= 2)
//   neg(i) = ids[j1] != m ? j1 : j2                   (needs nvalid > count[m])
// ---------------------------------------------------------------------------
__global__ void dist_kernel(const float* __restrict__ feats,
                            const int*   __restrict__ ids,
                            float*       __restrict__ out,
                            int out_size)
{
    const int bk    = blockIdx.x;
    const int b     = bk / CHUNKS;
    const int chunk = bk % CHUNKS;
    const int wid   = threadIdx.x >> 5;
    const int lane  = threadIdx.x & 31;
    const int t     = threadIdx.x;

    __shared__ int s_first[NIDS];
    __shared__ int s_second[NIDS];
    __shared__ int s_count[NIDS];
    __shared__ int s_j1;      // first valid index overall
    __shared__ int s_j2;      // first valid index with id != ids[j1]
    __shared__ int s_idj1;    // ids[j1]
    __shared__ int s_nvalid;
    __shared__ float s_tot;
    __shared__ int   s_cnt;
    __shared__ int   s_last;

    if (t < NIDS) {
        s_first[t]  = 0x7fffffff;
        s_second[t] = 0x7fffffff;
        s_count[t]  = 0;
    }
    if (t == 0) {
        s_j1 = 0x7fffffff;
        s_j2 = 0x7fffffff;
        s_nvalid = 0;
        s_tot = 0.0f;
        s_cnt = 0;
        s_last = 0;
    }
    __syncthreads();

    // Pass 1: first occurrence per id, per-id counts, first valid overall.
    const int i0  = t;
    const int i1  = t + DTHREADS;
    const int id0 = ids[b * NPTS + i0];
    const int id1 = ids[b * NPTS + i1];
    if (id0 >= 0) {
        atomicMin(&s_first[id0], i0);
        atomicAdd(&s_count[id0], 1);
        atomicMin(&s_j1, i0);
    }
    if (id1 >= 0) {
        atomicMin(&s_first[id1], i1);
        atomicAdd(&s_count[id1], 1);
        atomicMin(&s_j1, i1);
    }
    int nv = __syncthreads_count(id0 >= 0);
    nv    += __syncthreads_count(id1 >= 0);
    if (t == 0) {
        s_nvalid = nv;
        s_idj1 = (s_j1 < NPTS) ? ids[b * NPTS + s_j1] : -2;
    }
    __syncthreads();

    // Pass 2: second occurrence per id; first valid with id != ids[j1].
    const int idj1 = s_idj1;
    if (id0 >= 0) {
        if (i0 != s_first[id0]) atomicMin(&s_second[id0], i0);
        if (id0 != idj1)        atomicMin(&s_j2, i0);
    }
    if (id1 >= 0) {
        if (i1 != s_first[id1]) atomicMin(&s_second[id1], i1);
        if (id1 != idj1)        atomicMin(&s_j2, i1);
    }
    __syncthreads();

    const int nvalid = s_nvalid;
    const int j1 = s_j1;
    const int j2 = s_j2;

    float w_tot = 0.0f;
    int   w_cnt = 0;

    const int a_base = chunk * (NPTS / CHUNKS) + wid * APW;
    const float eps = c_eps;

    for (int a = 0; a < APW; ++a) {
        const int i = a_base + a;
        const int m = ids[b * NPTS + i];          // hot in L1/L2
        if (m < 0) continue;
        const int cm = s_count[m];
        if (cm < 2) continue;                      // no positive
        if (nvalid - cm < 1) continue;             // no negative

        const int f = s_first[m];
        const int p = (f != i) ? f : s_second[m];
        const int n = (idj1 != m) ? j1 : j2;

        const float4* __restrict__ fi =
            (const float4*)(feats + ((size_t)b * NPTS + i) * DIM);
        const float4* __restrict__ fp =
            (const float4*)(feats + ((size_t)b * NPTS + p) * DIM);
        const float4* __restrict__ fn =
            (const float4*)(feats + ((size_t)b * NPTS + n) * DIM);

        float sap = 0.0f, san = 0.0f;
        #pragma unroll
        for (int k = 0; k < DIM / 4 / 32; ++k) {
            const int idx = k * 32 + lane;
            const float4 a4 = fi[idx];
            const float4 p4 = fp[idx];
            const float4 n4 = fn[idx];
            float d;
            d = a4.x - p4.x + eps; sap = fmaf(d, d, sap);
            d = a4.y - p4.y + eps; sap = fmaf(d, d, sap);
            d = a4.z - p4.z + eps; sap = fmaf(d, d, sap);
            d = a4.w - p4.w + eps; sap = fmaf(d, d, sap);
            d = a4.x - n4.x + eps; san = fmaf(d, d, san);
            d = a4.y - n4.y + eps; san = fmaf(d, d, san);
            d = a4.z - n4.z + eps; san = fmaf(d, d, san);
            d = a4.w - n4.w + eps; san = fmaf(d, d, san);
        }
        #pragma unroll
        for (int o = 16; o > 0; o >>= 1) {
            sap += __shfl_xor_sync(0xFFFFFFFFu, sap, o);
            san += __shfl_xor_sync(0xFFFFFFFFu, san, o);
        }
        if (lane == 0) {
            const float per = sqrtf(sap) - sqrtf(san) + c_margin;
            if (per > 0.0f) w_tot += per;
            w_cnt++;
        }
    }

    if (lane == 0) {
        atomicAdd(&s_tot, w_tot);
        atomicAdd(&s_cnt, w_cnt);
    }
    __syncthreads();

    // Publish partial, grab ticket; the last block finishes the job.
    if (t == 0) {
        g_partial[bk] = s_tot;
        g_cnt[bk]     = s_cnt;
        __threadfence();
        const unsigned int old = atomicAdd(&g_ticket, 1u);
        s_last = (old == DBLOCKS - 1);
    }
    __syncthreads();

    if (s_last) {
        // Deterministic final reduction in registers + warp shuffles.
        // Each thread strided-sums 4 partials; then butterfly within warp;
        // then warp leaders combine via the (now free) shared atomics slots.
        float tot = 0.0f;
        int   cnt = 0;
        #pragma unroll
        for (int r = 0; r < DBLOCKS / DTHREADS; ++r) {
            tot += g_partial[r * DTHREADS + t];
            cnt += g_cnt[r * DTHREADS + t];
        }
        #pragma unroll
        for (int o = 16; o > 0; o >>= 1) {
            tot += __shfl_xor_sync(0xFFFFFFFFu, tot, o);
            cnt += __shfl_xor_sync(0xFFFFFFFFu, cnt, o);
        }
        __shared__ float s_wt[DWARPS];
        __shared__ int   s_wc[DWARPS];
        if (lane == 0) { s_wt[wid] = tot; s_wc[wid] = cnt; }
        __syncthreads();
        if (t == 0) {
            float T = 0.0f; int C = 0;
            #pragma unroll
            for (int w = 0; w < DWARPS; ++w) { T += s_wt[w]; C += s_wc[w]; }
            const float loss = (C > 0) ? (T / (float)C) : 0.0f;
            if (out_size > 0) out[0] = loss;   // tracking_loss
            if (out_size > 1) out[1] = loss;   // loss_triplet
            if (out_size > 2) out[2] = 0.0f;   // loss_id
            g_ticket = 0;                      // reset for next graph replay
            __threadfence();
        }
    }
}

extern "C" void kernel_launch(void* const* d_in, const int* in_sizes, int n_in,
                              void* d_out, int out_size)
{
    const float* feats = (const float*)d_in[0];
    const int*   ids   = (const int*)d_in[1];
    float*       out   = (float*)d_out;

    dist_kernel<<<DBLOCKS, DTHREADS>>>(feats, ids, out, out_size);
}